// round 13
// baseline (speedup 1.0000x reference)
#include <cuda_runtime.h>
#include <cuda_bf16.h>

#define IMG_W 1024
#define IMG_H 1024
#define NC_TOTAL 48
#define CHUNK 16           // consecutive 8-row tiles per CTA (128 rows)

// One tile: inputs cur[0..9] = rows y0-1..y0+8, outputs rows y0..y0+7.
// If PRE, prefetch next tile's 8 new rows (y0+9..y0+16) one per iteration r=2..9.
template<bool PRE>
__device__ __forceinline__ void do_tile(
    const float* __restrict__ base, float* __restrict__ op, int y0,
    float4 (&cur)[10], float4 (&nxt)[8], const float (&w)[9],
    int lane, int x0)
{
    float num[8][4], sq[8][4];

    // prologue halo for input row 0 (global row y0-1)
    float h0c = __shfl_up_sync(0xffffffffu, cur[0].w, 1);
    float h5c = __shfl_down_sync(0xffffffffu, cur[0].x, 1);
    {
        const int rr = y0 - 1;
        if (lane == 0)  h0c = (x0 > 0 && rr >= 0)          ? __ldg(base + (size_t)rr * IMG_W - 1) : 0.f;
        if (lane == 31) h5c = (x0 + 4 < IMG_W && rr >= 0)  ? __ldg(base + (size_t)rr * IMG_W + 4) : 0.f;
    }

#pragma unroll
    for (int r = 0; r < 10; r++) {
        // rolling prefetch: one row of next tile per iteration (consumed next tile)
        if (PRE && r >= 2) {
            const int rr = y0 + 7 + r;                 // y0+9 .. y0+16
            const int rc = min(IMG_H - 1, rr);
            nxt[r - 2] = *reinterpret_cast<const float4*>(base + (size_t)rc * IMG_W);
        }

        // next row's halo pipelined ahead of this row's compute
        float h0n = 0.f, h5n = 0.f;
        if (r + 1 < 10) {
            h0n = __shfl_up_sync(0xffffffffu, cur[r + 1].w, 1);
            h5n = __shfl_down_sync(0xffffffffu, cur[r + 1].x, 1);
            const int rr = y0 + r;                     // global row of cur[r+1]
            if (lane == 0)  h0n = (x0 > 0 && rr < IMG_H)         ? __ldg(base + (size_t)rr * IMG_W - 1) : 0.f;
            if (lane == 31) h5n = (x0 + 4 < IMG_W && rr < IMG_H) ? __ldg(base + (size_t)rr * IMG_W + 4) : 0.f;
        }

        const float a[6] = { h0c, cur[r].x, cur[r].y, cur[r].z, cur[r].w, h5c };

        float p[6];
#pragma unroll
        for (int i = 0; i < 6; i++) p[i] = a[i] * a[i];
        const float u = p[1] + p[2];
        const float t = p[3] + p[4];
        const float s[4] = { p[0] + u, u + p[3], p[2] + t, t + p[5] };

#pragma unroll
        for (int o = 0; o < 8; o++) {
            const int k = r - o;
            if (k == 0) {
#pragma unroll
                for (int j = 0; j < 4; j++) {
                    num[o][j] = fmaf(w[0], a[j], fmaf(w[1], a[j + 1], w[2] * a[j + 2]));
                    sq[o][j] = s[j];
                }
            } else if (k == 1 || k == 2) {
                const float w0 = w[k * 3 + 0], w1 = w[k * 3 + 1], w2 = w[k * 3 + 2];
#pragma unroll
                for (int j = 0; j < 4; j++) {
                    num[o][j] = fmaf(w0, a[j], fmaf(w1, a[j + 1], fmaf(w2, a[j + 2], num[o][j])));
                    sq[o][j] += s[j];
                }
            }
        }

        if (r >= 2) {
            const int o = r - 2;
            float4 ov;
            ov.x = num[o][0] * rsqrtf(sq[o][0]);
            ov.y = num[o][1] * rsqrtf(sq[o][1]);
            ov.z = num[o][2] * rsqrtf(sq[o][2]);
            ov.w = num[o][3] * rsqrtf(sq[o][3]);
            *reinterpret_cast<float4*>(op + (size_t)o * IMG_W) = ov;
        }

        h0c = h0n; h5c = h5n;
    }
}

// v11: persistent rolling pipeline. CTA = one 128-row chunk (16 consecutive
// 8-row tiles) of one (n,c) image. Fresh 10-row batch only at chunk start;
// thereafter 8 new rows/tile stream in one-per-iteration, 2 rows reused.
__global__ void __launch_bounds__(256, 3) normconv3x3_v11(
    const float* __restrict__ x,
    const float* __restrict__ wt,
    float* __restrict__ out)
{
    const int lane = threadIdx.x & 31;
    const int x0 = (int)threadIdx.x << 2;          // 0..1020
    const int b = blockIdx.x;
    const int nc = b >> 3;                         // 0..47
    const int ycs = (b & 7) << 7;                  // chunk start row (0,128,...,896)
    const int c = nc % 3;

    const float* base = x + ((size_t)nc << 20) + x0;
    float* outnc = out + ((size_t)nc << 20) + x0;

    // ---- chunk-start fresh batch: rows ycs-1 .. ycs+8 (clamped+masked) ----
    float4 cur[10], nxt[8];
#pragma unroll
    for (int i = 0; i < 10; i++) {
        const int rr = ycs - 1 + i;
        const int rc = min(IMG_H - 1, max(0, rr));
        cur[i] = *reinterpret_cast<const float4*>(base + (size_t)rc * IMG_W);
        if (rr != rc) cur[i] = make_float4(0.f, 0.f, 0.f, 0.f);
    }

    // weights after the batch is in flight
    float w[9];
    float ws2 = 0.f;
#pragma unroll
    for (int k = 0; k < 9; k++) { w[k] = __ldg(&wt[c * 9 + k]); ws2 += w[k] * w[k]; }
    const float winv = rsqrtf(ws2);
#pragma unroll
    for (int k = 0; k < 9; k++) w[k] *= winv;

    for (int t = 0; t < CHUNK - 1; t++) {
        const int y0 = ycs + (t << 3);
        do_tile<true>(base, outnc + (size_t)y0 * IMG_W, y0, cur, nxt, w, lane, x0);

        // roll the window: rows y0+7,y0+8 reused; 8 prefetched rows shift in
        cur[0] = cur[8];
        cur[1] = cur[9];
#pragma unroll
        for (int i = 0; i < 8; i++) cur[2 + i] = nxt[i];
        // bottom edge: prefetched row y0+16 was clamped; zero it if outside
        if (y0 + 16 >= IMG_H) cur[9] = make_float4(0.f, 0.f, 0.f, 0.f);
    }
    {
        const int y0 = ycs + ((CHUNK - 1) << 3);
        do_tile<false>(base, outnc + (size_t)y0 * IMG_W, y0, cur, nxt, w, lane, x0);
    }
}

extern "C" void kernel_launch(void* const* d_in, const int* in_sizes, int n_in,
                              void* d_out, int out_size) {
    const float* x  = (const float*)d_in[0];
    const float* wt = (const float*)d_in[1];
    float* out = (float*)d_out;

    dim3 grid(NC_TOTAL * (IMG_H / (CHUNK * 8)));   // 48 * 8 = 384 CTAs
    normconv3x3_v11<<<grid, 256>>>(x, wt, out);
}

// round 14
// speedup vs baseline: 1.3760x; 1.3760x over previous
#include <cuda_runtime.h>
#include <cuda_bf16.h>

#define IMG_W 1024
#define IMG_H 1024
#define NC_TOTAL 48
#define ROWS 8
#define NLOAD (ROWS + 2)
#define NTILES (NC_TOTAL * (IMG_H / ROWS))   // 6144
#define GRID_CTAS 456                        // 3 CTAs/SM x 152 SMs (GB300)

// v12 = v7 tile body VERBATIM (proven fastest: 10 front-batched row loads,
// 8-row tile, pipelined shuffle halo, early store), wrapped in a persistent
// grid-stride loop: 456 CTAs, ~13-14 tiles each. Removes ~13 wave transitions.
__device__ __forceinline__ void tile8(
    const float* __restrict__ x, const float* __restrict__ wt,
    float* __restrict__ out, int tile, int lane, int x0)
{
    const int y0 = (tile & 127) << 3;              // 128 8-row tiles
    const int nc = tile >> 7;                      // 0..47
    const int c = nc % 3;

    const float* base = x + ((size_t)nc << 20) + x0;

    // ---- Phase 1: 10 branch-free batched row loads (MLP=10) ----
    float4 v[NLOAD];
    if (y0 != 0 && y0 != IMG_H - ROWS) {
#pragma unroll
        for (int r = 0; r < NLOAD; r++)
            v[r] = *reinterpret_cast<const float4*>(base + (size_t)(y0 - 1 + r) * IMG_W);
    } else {
#pragma unroll
        for (int r = 0; r < NLOAD; r++) {
            const int rr = y0 - 1 + r;
            const int rc = min(IMG_H - 1, max(0, rr));
            v[r] = *reinterpret_cast<const float4*>(base + (size_t)rc * IMG_W);
            if (rr != rc) v[r] = make_float4(0.f, 0.f, 0.f, 0.f);
        }
    }

    // Weights after the bulk loads are in flight (const-cache hits)
    float w[9];
    float ws2 = 0.f;
#pragma unroll
    for (int k = 0; k < 9; k++) { w[k] = __ldg(&wt[c * 9 + k]); ws2 += w[k] * w[k]; }
    const float winv = rsqrtf(ws2);
#pragma unroll
    for (int k = 0; k < 9; k++) w[k] *= winv;

    float num[ROWS][4], sq[ROWS][4];
    float* op = out + ((size_t)nc << 20) + (size_t)y0 * IMG_W + x0;

    // Prologue halo for input row 0 (global row y0-1)
    float h0c = __shfl_up_sync(0xffffffffu, v[0].w, 1);
    float h5c = __shfl_down_sync(0xffffffffu, v[0].x, 1);
    {
        const int rr = y0 - 1;
        if (lane == 0)  h0c = (x0 > 0 && rr >= 0)          ? __ldg(base + (size_t)rr * IMG_W - 1) : 0.f;
        if (lane == 31) h5c = (x0 + 4 < IMG_W && rr >= 0)  ? __ldg(base + (size_t)rr * IMG_W + 4) : 0.f;
    }

#pragma unroll
    for (int r = 0; r < NLOAD; r++) {
        // next row's halo pipelined ahead of this row's compute
        float h0n = 0.f, h5n = 0.f;
        if (r + 1 < NLOAD) {
            h0n = __shfl_up_sync(0xffffffffu, v[r + 1].w, 1);
            h5n = __shfl_down_sync(0xffffffffu, v[r + 1].x, 1);
            const int rr = y0 + r;                 // global row of v[r+1]
            if (lane == 0)  h0n = (x0 > 0 && rr < IMG_H)         ? __ldg(base + (size_t)rr * IMG_W - 1) : 0.f;
            if (lane == 31) h5n = (x0 + 4 < IMG_W && rr < IMG_H) ? __ldg(base + (size_t)rr * IMG_W + 4) : 0.f;
        }

        const float a[6] = { h0c, v[r].x, v[r].y, v[r].z, v[r].w, h5c };

        float p[6];
#pragma unroll
        for (int i = 0; i < 6; i++) p[i] = a[i] * a[i];
        const float u = p[1] + p[2];
        const float t = p[3] + p[4];
        const float s[4] = { p[0] + u, u + p[3], p[2] + t, t + p[5] };

#pragma unroll
        for (int o = 0; o < ROWS; o++) {
            const int k = r - o;                    // weight row for this (input,output) pair
            if (k == 0) {
#pragma unroll
                for (int j = 0; j < 4; j++) {
                    num[o][j] = fmaf(w[0], a[j], fmaf(w[1], a[j + 1], w[2] * a[j + 2]));
                    sq[o][j] = s[j];
                }
            } else if (k == 1 || k == 2) {
                const float w0 = w[k * 3 + 0], w1 = w[k * 3 + 1], w2 = w[k * 3 + 2];
#pragma unroll
                for (int j = 0; j < 4; j++) {
                    num[o][j] = fmaf(w0, a[j], fmaf(w1, a[j + 1], fmaf(w2, a[j + 2], num[o][j])));
                    sq[o][j] += s[j];
                }
            }
        }

        // output row (r-2) complete after consuming input row r
        if (r >= 2) {
            const int o = r - 2;
            float4 ov;
            ov.x = num[o][0] * rsqrtf(sq[o][0]);
            ov.y = num[o][1] * rsqrtf(sq[o][1]);
            ov.z = num[o][2] * rsqrtf(sq[o][2]);
            ov.w = num[o][3] * rsqrtf(sq[o][3]);
            // streaming store: output is never re-read; don't pollute L2
            __stcs(reinterpret_cast<float4*>(op + (size_t)o * IMG_W), ov);
        }

        h0c = h0n; h5c = h5n;
    }
}

__global__ void __launch_bounds__(256, 3) normconv3x3_v12(
    const float* __restrict__ x,
    const float* __restrict__ wt,
    float* __restrict__ out)
{
    const int lane = threadIdx.x & 31;
    const int x0 = (int)threadIdx.x << 2;          // 0..1020

    for (int tile = blockIdx.x; tile < NTILES; tile += GRID_CTAS)
        tile8(x, wt, out, tile, lane, x0);
}

extern "C" void kernel_launch(void* const* d_in, const int* in_sizes, int n_in,
                              void* d_out, int out_size) {
    const float* x  = (const float*)d_in[0];
    const float* wt = (const float*)d_in[1];
    float* out = (float*)d_out;

    normconv3x3_v12<<<GRID_CTAS, 256>>>(x, wt, out);
}